// round 4
// baseline (speedup 1.0000x reference)
#include <cuda_runtime.h>
#include <math.h>

// ---------------------------------------------------------------------------
// N=100000, F_in=128, F_hid=64, F_out=40, E=1600000 (+N self loops).
// ---------------------------------------------------------------------------
#define MAXN 100000
#define MAXE 1700096

__device__ float g_h1[(size_t)MAXN * 64];    // gemm1 output
__device__ float g_h1r[(size_t)MAXN * 64];   // layer-1 agg output (rectified)
__device__ float g_h2[(size_t)MAXN * 40];    // gemm2 output
__device__ float g_as[MAXN];
__device__ float g_ad[MAXN];
__device__ int   g_idx[2 * 1600000];         // normalized int32 src|dst
__device__ int   g_cnt[MAXN];                // degree histogram
__device__ int   g_off[MAXN + 1];            // CSR offsets
__device__ int   g_cur[MAXN];                // fill cursors
__device__ int   g_srcs[MAXE];               // CSR: src sorted by dst
__device__ int   g_bsum[128];                // scan partials
__device__ int   g_is64;

// ---------------------------------------------------------------------------
// Edge index dtype detection + conversion (int64 vs int32 -> int32),
// with destination histogram fused into the conversion.
// ---------------------------------------------------------------------------
__global__ void detect_idx_kernel(const unsigned int* __restrict__ w, int* flag) {
    __shared__ int any;
    if (threadIdx.x == 0) any = 0;
    __syncthreads();
    for (int i = threadIdx.x; i < 1024; i += blockDim.x)
        if (w[2 * i + 1] != 0u) atomicOr(&any, 1);
    __syncthreads();
    if (threadIdx.x == 0) *flag = any ? 0 : 1;  // 1 => int64
}

__global__ void init_cnt_kernel(int* cnt, int n) {
    int i = blockIdx.x * blockDim.x + threadIdx.x;
    if (i < n) cnt[i] = 1;  // self loop
}

__global__ void convert_hist_kernel(const unsigned int* __restrict__ w,
                                    int* __restrict__ out, int* __restrict__ cnt,
                                    long long n2, long long E,
                                    const int* __restrict__ flag) {
    long long i = (long long)blockIdx.x * blockDim.x + threadIdx.x;
    if (i >= n2) return;
    int is64 = *flag;
    int v = (int)(is64 ? w[2 * i] : w[i]);
    out[i] = v;
    if (i >= E) atomicAdd(&cnt[v], 1);   // dst half
}

// ---------------------------------------------------------------------------
// Two-level exclusive scan of cnt -> off  (N <= 128*1024)
// ---------------------------------------------------------------------------
__global__ void scanA_kernel(const int* __restrict__ cnt, int* __restrict__ off,
                             int* __restrict__ bsum, int n) {
    __shared__ int sm[1024];
    int i = blockIdx.x * 1024 + threadIdx.x;
    int v = (i < n) ? cnt[i] : 0;
    sm[threadIdx.x] = v;
    __syncthreads();
    #pragma unroll
    for (int o = 1; o < 1024; o <<= 1) {
        int t = (threadIdx.x >= o) ? sm[threadIdx.x - o] : 0;
        __syncthreads();
        sm[threadIdx.x] += t;
        __syncthreads();
    }
    if (i < n) off[i] = sm[threadIdx.x] - v;           // exclusive
    if (threadIdx.x == 1023) bsum[blockIdx.x] = sm[1023];
}

__global__ void scanB_kernel(int* bsum, int nb) {
    __shared__ int sm[128];
    int v = (threadIdx.x < nb) ? bsum[threadIdx.x] : 0;
    sm[threadIdx.x] = v;
    __syncthreads();
    #pragma unroll
    for (int o = 1; o < 128; o <<= 1) {
        int t = (threadIdx.x >= o) ? sm[threadIdx.x - o] : 0;
        __syncthreads();
        sm[threadIdx.x] += t;
        __syncthreads();
    }
    if (threadIdx.x < nb) bsum[threadIdx.x] = sm[threadIdx.x] - v;  // exclusive
}

__global__ void scanC_kernel(int* __restrict__ off, int* __restrict__ cur,
                             const int* __restrict__ bsum, int n, int total) {
    int i = blockIdx.x * blockDim.x + threadIdx.x;
    if (i < n) {
        int o = off[i] + bsum[i >> 10];
        off[i] = o;
        cur[i] = o;
    }
    if (i == 0) off[n] = total;
}

__global__ void fill_kernel(const int* __restrict__ idx, int* __restrict__ cur,
                            int* __restrict__ srcs, long long E, long long T) {
    long long t = (long long)blockIdx.x * blockDim.x + threadIdx.x;
    if (t >= T) return;
    int s, d;
    if (t < E) { s = idx[t]; d = idx[t + E]; } else { s = d = (int)(t - E); }
    int pos = atomicAdd(&cur[d], 1);
    srcs[pos] = s;
}

// ---------------------------------------------------------------------------
// GEMM1: h = x @ W (K=128, C=64). 128 rows x 64 cols per block, 128 threads,
// 8x8 tile per thread, packed f32x2 FMAs, K chunked by 32.
// X swizzled per 8-row group for conflict-free column reads.
// ---------------------------------------------------------------------------
__global__ void gemm1_kernel(const float* __restrict__ x,
                             const float* __restrict__ W,
                             float* __restrict__ h, int Nn) {
    __shared__ float Xs[128 * 32];   // 16 KB (swizzled)
    __shared__ float Ws[32 * 64];    // 8 KB
    int tid = threadIdx.x;
    int row0 = blockIdx.x * 128;
    int rt = tid >> 3;               // 0..15 -> rows rt*8..+7
    int ct = tid & 7;                // 0..7  -> cols ct*8..+7
    int r0 = rt * 8;
    int kx = (rt & 3) << 3;          // swizzle key for this thread's row group

    unsigned long long acc[8][4];
    #pragma unroll
    for (int i = 0; i < 8; i++)
        #pragma unroll
        for (int j = 0; j < 4; j++) acc[i][j] = 0ull;

    const float4* x4 = (const float4*)x;

    for (int kc = 0; kc < 4; kc++) {
        // W chunk rows [kc*32, +32): 512 float4
        const float4* W4 = (const float4*)(W + kc * 32 * 64);
        #pragma unroll
        for (int i = tid; i < 512; i += 128) ((float4*)Ws)[i] = W4[i];
        // X chunk: 128 rows x 8 float4, swizzled store
        #pragma unroll
        for (int i = tid; i < 1024; i += 128) {
            int row = i >> 3;
            int c4  = i & 7;
            int gr = row0 + row;
            float4 v = (gr < Nn) ? x4[(size_t)gr * 32 + kc * 8 + c4]
                                 : make_float4(0.f, 0.f, 0.f, 0.f);
            int col = (c4 * 4) ^ (((row >> 3) & 3) << 3);
            *(float4*)&Xs[row * 32 + col] = v;
        }
        __syncthreads();

        #pragma unroll
        for (int k = 0; k < 32; k++) {
            longlong2 w0 = *(const longlong2*)&Ws[k * 64 + ct * 8];
            longlong2 w1 = *(const longlong2*)&Ws[k * 64 + ct * 8 + 4];
            #pragma unroll
            for (int i = 0; i < 8; i++) {
                float xv = Xs[(r0 + i) * 32 + (k ^ kx)];
                unsigned long long xx;
                asm("mov.b64 %0, {%1, %1};" : "=l"(xx) : "r"(__float_as_uint(xv)));
                asm("fma.rn.f32x2 %0, %1, %2, %0;" : "+l"(acc[i][0]) : "l"(xx), "l"((unsigned long long)w0.x));
                asm("fma.rn.f32x2 %0, %1, %2, %0;" : "+l"(acc[i][1]) : "l"(xx), "l"((unsigned long long)w0.y));
                asm("fma.rn.f32x2 %0, %1, %2, %0;" : "+l"(acc[i][2]) : "l"(xx), "l"((unsigned long long)w1.x));
                asm("fma.rn.f32x2 %0, %1, %2, %0;" : "+l"(acc[i][3]) : "l"(xx), "l"((unsigned long long)w1.y));
            }
        }
        __syncthreads();
    }

    #pragma unroll
    for (int i = 0; i < 8; i++) {
        int row = row0 + r0 + i;
        if (row < Nn) {
            float* dstp = h + (size_t)row * 64 + ct * 8;
            *(longlong2*)dstp       = make_longlong2((long long)acc[i][0], (long long)acc[i][1]);
            *(longlong2*)(dstp + 4) = make_longlong2((long long)acc[i][2], (long long)acc[i][3]);
        }
    }
}

// ---------------------------------------------------------------------------
// GEMM2: h2 = h1r @ W2  (K=64, C=40)
// ---------------------------------------------------------------------------
__global__ void gemm2_kernel(const float* __restrict__ x,
                             const float* __restrict__ W,
                             float* __restrict__ h, int Nn) {
    __shared__ float Xs[32][64];
    __shared__ float Ws[64][40];
    int tid = threadIdx.x;
    int row0 = blockIdx.x * 32;

    #pragma unroll
    for (int i = tid; i < 64 * 40; i += 128) Ws[i / 40][i % 40] = W[i];

    const float4* x4 = (const float4*)x;
    float4* Xs4 = (float4*)Xs;
    #pragma unroll
    for (int i = tid; i < 32 * 16; i += 128) {
        long long gi = (long long)row0 * 16 + i;
        Xs4[i] = (gi < (long long)Nn * 16) ? x4[gi] : make_float4(0.f, 0.f, 0.f, 0.f);
    }
    __syncthreads();

    int r0 = (tid >> 3) * 2;
    int c0 = (tid & 7) * 5;
    float acc[2][5] = {};
    #pragma unroll 4
    for (int k = 0; k < 64; k++) {
        float xv0 = Xs[r0][k];
        float xv1 = Xs[r0 + 1][k];
        #pragma unroll
        for (int j = 0; j < 5; j++) {
            float wv = Ws[k][c0 + j];
            acc[0][j] += xv0 * wv;
            acc[1][j] += xv1 * wv;
        }
    }
    #pragma unroll
    for (int i = 0; i < 2; i++) {
        int row = row0 + r0 + i;
        if (row < Nn) {
            float* dstp = h + (size_t)row * 40 + c0;
            #pragma unroll
            for (int j = 0; j < 5; j++) dstp[j] = acc[i][j];
        }
    }
}

// ---------------------------------------------------------------------------
// Alpha: per-node dot products with a_src / a_dst. One warp per node.
// ---------------------------------------------------------------------------
__global__ void alpha_kernel(const float* __restrict__ h,
                             const float* __restrict__ asrc,
                             const float* __restrict__ adst,
                             float* __restrict__ outs, float* __restrict__ outd,
                             int Nn, int F) {
    int warp = (blockIdx.x * blockDim.x + threadIdx.x) >> 5;
    int lane = threadIdx.x & 31;
    if (warp >= Nn) return;
    float s = 0.f, d = 0.f;
    for (int c = lane; c < F; c += 32) {
        float v = h[(size_t)warp * F + c];
        s += v * asrc[c];
        d += v * adst[c];
    }
    #pragma unroll
    for (int o = 16; o; o >>= 1) {
        s += __shfl_xor_sync(0xffffffffu, s, o);
        d += __shfl_xor_sync(0xffffffffu, d, o);
    }
    if (lane == 0) { outs[warp] = s; outd[warp] = d; }
}

// ---------------------------------------------------------------------------
// Fused GAT aggregation: one warp per destination node (CSR).
// Pass 1: Sum exp(leakyrelu(as[src]+ad[d])) over the node's edges (registers).
// Pass 2: gather h[src] rows with float2 lanes, FMA into register accumulator.
// Epilogue: FINAL=false -> relu(acc+bias) stored; FINAL=true -> log_softmax.
// ---------------------------------------------------------------------------
template <int F, bool FINAL>
__global__ void gat_agg_kernel(const int* __restrict__ srcs,
                               const int* __restrict__ off,
                               const float* __restrict__ as_,
                               const float* __restrict__ ad_,
                               const float* __restrict__ h,
                               const float* __restrict__ bias,
                               float* __restrict__ outp, int Nn) {
    constexpr int HALF = F / 2;
    int d = (blockIdx.x * blockDim.x + threadIdx.x) >> 5;
    int lane = threadIdx.x & 31;
    if (d >= Nn) return;
    int beg = off[d], end = off[d + 1];
    int deg = end - beg;
    float adv = ad_[d];

    float ex[4];
    int sv[4];
    float sum = 0.f;
    int nc = (deg + 31) >> 5;
    bool small = (nc <= 4);

    if (small) {
        #pragma unroll
        for (int c = 0; c < 4; c++) {
            int i = beg + c * 32 + lane;
            float xv = 0.f;
            int s = 0;
            if (i < end) {
                s = srcs[i];
                float e = as_[s] + adv;
                e = (e > 0.f) ? e : 0.2f * e;
                xv = expf(e);
            }
            ex[c] = xv;
            sv[c] = s;
            sum += xv;
        }
    } else {
        for (int i = beg + lane; i < end; i += 32) {
            int s = srcs[i];
            float e = as_[s] + adv;
            e = (e > 0.f) ? e : 0.2f * e;
            sum += expf(e);
        }
    }
    #pragma unroll
    for (int o = 16; o; o >>= 1) sum += __shfl_xor_sync(0xffffffffu, sum, o);
    float rden = 1.0f / sum;

    float2 acc = make_float2(0.f, 0.f);
    const float2* h2 = (const float2*)h;

    if (small) {
        #pragma unroll
        for (int c = 0; c < 4; c++) {
            if (c * 32 >= deg) break;
            int cnt = min(32, deg - c * 32);
            for (int j = 0; j < cnt; j++) {
                float coef = __shfl_sync(0xffffffffu, ex[c], j) * rden;
                int s = __shfl_sync(0xffffffffu, sv[c], j);
                if (lane < HALF) {
                    float2 hv = __ldg(&h2[(size_t)s * HALF + lane]);
                    acc.x = fmaf(hv.x, coef, acc.x);
                    acc.y = fmaf(hv.y, coef, acc.y);
                }
            }
        }
    } else {
        for (int i = beg; i < end; i++) {
            int s = srcs[i];
            float e = as_[s] + adv;
            e = (e > 0.f) ? e : 0.2f * e;
            float coef = expf(e) * rden;
            if (lane < HALF) {
                float2 hv = __ldg(&h2[(size_t)s * HALF + lane]);
                acc.x = fmaf(hv.x, coef, acc.x);
                acc.y = fmaf(hv.y, coef, acc.y);
            }
        }
    }

    if (!FINAL) {
        if (lane < HALF) {
            float2 bb = ((const float2*)bias)[lane];
            ((float2*)outp)[(size_t)d * HALF + lane] =
                make_float2(fmaxf(acc.x + bb.x, 0.f), fmaxf(acc.y + bb.y, 0.f));
        }
    } else {
        float vx = __int_as_float(0xff800000), vy = vx;
        if (lane < HALF) {
            float2 bb = ((const float2*)bias)[lane];
            vx = acc.x + bb.x;
            vy = acc.y + bb.y;
        }
        float mx = fmaxf(vx, vy);
        #pragma unroll
        for (int o = 16; o; o >>= 1) mx = fmaxf(mx, __shfl_xor_sync(0xffffffffu, mx, o));
        float se = (lane < HALF) ? (expf(vx - mx) + expf(vy - mx)) : 0.f;
        #pragma unroll
        for (int o = 16; o; o >>= 1) se += __shfl_xor_sync(0xffffffffu, se, o);
        float ls = mx + logf(se);
        if (lane < HALF)
            ((float2*)outp)[(size_t)d * HALF + lane] = make_float2(vx - ls, vy - ls);
    }
}

// ---------------------------------------------------------------------------
// Launch
// ---------------------------------------------------------------------------
extern "C" void kernel_launch(void* const* d_in, const int* in_sizes, int n_in,
                              void* d_out, int out_size) {
    const float* x       = (const float*)d_in[0];
    const unsigned int* ei_raw = (const unsigned int*)d_in[1];
    const float* W1      = (const float*)d_in[2];
    const float* a_src1  = (const float*)d_in[3];
    const float* a_dst1  = (const float*)d_in[4];
    const float* b1      = (const float*)d_in[5];
    const float* W2      = (const float*)d_in[6];
    const float* a_src2  = (const float*)d_in[7];
    const float* a_dst2  = (const float*)d_in[8];
    const float* b2      = (const float*)d_in[9];
    float* out           = (float*)d_out;

    int Nn = in_sizes[0] / 128;
    long long E = in_sizes[1] / 2;
    long long T = E + Nn;

    float *p_h1, *p_h1r, *p_h2, *p_as, *p_ad;
    int *p_idx, *p_cnt, *p_off, *p_cur, *p_srcs, *p_bsum, *p_is64;
    cudaGetSymbolAddress((void**)&p_h1, g_h1);
    cudaGetSymbolAddress((void**)&p_h1r, g_h1r);
    cudaGetSymbolAddress((void**)&p_h2, g_h2);
    cudaGetSymbolAddress((void**)&p_as, g_as);
    cudaGetSymbolAddress((void**)&p_ad, g_ad);
    cudaGetSymbolAddress((void**)&p_idx, g_idx);
    cudaGetSymbolAddress((void**)&p_cnt, g_cnt);
    cudaGetSymbolAddress((void**)&p_off, g_off);
    cudaGetSymbolAddress((void**)&p_cur, g_cur);
    cudaGetSymbolAddress((void**)&p_srcs, g_srcs);
    cudaGetSymbolAddress((void**)&p_bsum, g_bsum);
    cudaGetSymbolAddress((void**)&p_is64, g_is64);

    const int TB = 256;
    int nb = (Nn + 1023) / 1024;

    // ---- CSR build ----
    detect_idx_kernel<<<1, 256>>>(ei_raw, p_is64);
    init_cnt_kernel<<<(Nn + TB - 1) / TB, TB>>>(p_cnt, Nn);
    convert_hist_kernel<<<(int)((2 * E + TB - 1) / TB), TB>>>(ei_raw, p_idx, p_cnt, 2 * E, E, p_is64);
    scanA_kernel<<<nb, 1024>>>(p_cnt, p_off, p_bsum, Nn);
    scanB_kernel<<<1, 128>>>(p_bsum, nb);
    scanC_kernel<<<(Nn + TB - 1) / TB, TB>>>(p_off, p_cur, p_bsum, Nn, (int)T);
    fill_kernel<<<(int)((T + TB - 1) / TB), TB>>>(p_idx, p_cur, p_srcs, E, T);

    // ---- Layer 1 ----
    gemm1_kernel<<<(Nn + 127) / 128, 128>>>(x, W1, p_h1, Nn);
    alpha_kernel<<<(Nn + 7) / 8, 256>>>(p_h1, a_src1, a_dst1, p_as, p_ad, Nn, 64);
    gat_agg_kernel<64, false><<<(Nn + 7) / 8, 256>>>(p_srcs, p_off, p_as, p_ad, p_h1, b1, p_h1r, Nn);

    // ---- Layer 2 ----
    gemm2_kernel<<<(Nn + 31) / 32, 128>>>(p_h1r, W2, p_h2, Nn);
    alpha_kernel<<<(Nn + 7) / 8, 256>>>(p_h2, a_src2, a_dst2, p_as, p_ad, Nn, 40);
    gat_agg_kernel<40, true><<<(Nn + 7) / 8, 256>>>(p_srcs, p_off, p_as, p_ad, p_h2, b2, out, Nn);
}

// round 5
// speedup vs baseline: 1.6802x; 1.6802x over previous
#include <cuda_runtime.h>
#include <math.h>

// ---------------------------------------------------------------------------
// N=100000, F_in=128, F_hid=64, F_out=40, E=1600000 (+N self loops).
// ---------------------------------------------------------------------------
#define MAXN 100000
#define MAXE 1700096

__device__ float g_h1[(size_t)MAXN * 64];    // gemm1 output
__device__ float g_h1r[(size_t)MAXN * 64];   // layer-1 agg output (rectified)
__device__ float g_h2[(size_t)MAXN * 40];    // gemm2 output
__device__ float g_as[MAXN];
__device__ float g_ad[MAXN];
__device__ int   g_idx[2 * 1600000];         // normalized int32 src|dst
__device__ int   g_cnt[MAXN];                // degree histogram
__device__ int   g_off[MAXN + 1];            // CSR offsets
__device__ int   g_cur[MAXN];                // fill cursors
__device__ int   g_srcs[MAXE];               // CSR: src sorted by dst
__device__ int   g_bsum[128];                // scan partials
__device__ int   g_is64;

// ---------------------------------------------------------------------------
// Edge index dtype detection + conversion, dst histogram fused.
// ---------------------------------------------------------------------------
__global__ void detect_idx_kernel(const unsigned int* __restrict__ w, int* flag) {
    __shared__ int any;
    if (threadIdx.x == 0) any = 0;
    __syncthreads();
    for (int i = threadIdx.x; i < 1024; i += blockDim.x)
        if (w[2 * i + 1] != 0u) atomicOr(&any, 1);
    __syncthreads();
    if (threadIdx.x == 0) *flag = any ? 0 : 1;  // 1 => int64
}

__global__ void init_cnt_kernel(int* cnt, int n) {
    int i = blockIdx.x * blockDim.x + threadIdx.x;
    if (i < n) cnt[i] = 1;  // self loop
}

__global__ void convert_hist_kernel(const unsigned int* __restrict__ w,
                                    int* __restrict__ out, int* __restrict__ cnt,
                                    long long n2, long long E,
                                    const int* __restrict__ flag) {
    long long i = (long long)blockIdx.x * blockDim.x + threadIdx.x;
    if (i >= n2) return;
    int is64 = *flag;
    int v = (int)(is64 ? w[2 * i] : w[i]);
    out[i] = v;
    if (i >= E) atomicAdd(&cnt[v], 1);   // dst half
}

// ---------------------------------------------------------------------------
// Two-level exclusive scan of cnt -> off
// ---------------------------------------------------------------------------
__global__ void scanA_kernel(const int* __restrict__ cnt, int* __restrict__ off,
                             int* __restrict__ bsum, int n) {
    __shared__ int sm[1024];
    int i = blockIdx.x * 1024 + threadIdx.x;
    int v = (i < n) ? cnt[i] : 0;
    sm[threadIdx.x] = v;
    __syncthreads();
    #pragma unroll
    for (int o = 1; o < 1024; o <<= 1) {
        int t = (threadIdx.x >= o) ? sm[threadIdx.x - o] : 0;
        __syncthreads();
        sm[threadIdx.x] += t;
        __syncthreads();
    }
    if (i < n) off[i] = sm[threadIdx.x] - v;
    if (threadIdx.x == 1023) bsum[blockIdx.x] = sm[1023];
}

__global__ void scanB_kernel(int* bsum, int nb) {
    __shared__ int sm[128];
    int v = (threadIdx.x < nb) ? bsum[threadIdx.x] : 0;
    sm[threadIdx.x] = v;
    __syncthreads();
    #pragma unroll
    for (int o = 1; o < 128; o <<= 1) {
        int t = (threadIdx.x >= o) ? sm[threadIdx.x - o] : 0;
        __syncthreads();
        sm[threadIdx.x] += t;
        __syncthreads();
    }
    if (threadIdx.x < nb) bsum[threadIdx.x] = sm[threadIdx.x] - v;
}

__global__ void scanC_kernel(int* __restrict__ off, int* __restrict__ cur,
                             const int* __restrict__ bsum, int n, int total) {
    int i = blockIdx.x * blockDim.x + threadIdx.x;
    if (i < n) {
        int o = off[i] + bsum[i >> 10];
        off[i] = o;
        cur[i] = o;
    }
    if (i == 0) off[n] = total;
}

__global__ void fill_kernel(const int* __restrict__ idx, int* __restrict__ cur,
                            int* __restrict__ srcs, long long E, long long T) {
    long long t = (long long)blockIdx.x * blockDim.x + threadIdx.x;
    if (t >= T) return;
    int s, d;
    if (t < E) { s = idx[t]; d = idx[t + E]; } else { s = d = (int)(t - E); }
    int pos = atomicAdd(&cur[d], 1);
    srcs[pos] = s;
}

// ---------------------------------------------------------------------------
// GEMM1: h = x @ W (K=128, C=64), 128x64 per block, 128 threads, 8x8/thread,
// packed f32x2 FMAs. Alpha dots (h.a_src / h.a_dst) fused into epilogue.
// ---------------------------------------------------------------------------
__global__ void gemm1_kernel(const float* __restrict__ x,
                             const float* __restrict__ W,
                             const float* __restrict__ asv,
                             const float* __restrict__ adv,
                             float* __restrict__ h,
                             float* __restrict__ as_, float* __restrict__ ad_,
                             int Nn) {
    __shared__ float Xs[128 * 32];
    __shared__ float Ws[32 * 64];
    int tid = threadIdx.x;
    int row0 = blockIdx.x * 128;
    int rt = tid >> 3;
    int ct = tid & 7;
    int r0 = rt * 8;
    int kx = (rt & 3) << 3;

    unsigned long long acc[8][4];
    #pragma unroll
    for (int i = 0; i < 8; i++)
        #pragma unroll
        for (int j = 0; j < 4; j++) acc[i][j] = 0ull;

    const float4* x4 = (const float4*)x;

    for (int kc = 0; kc < 4; kc++) {
        const float4* W4 = (const float4*)(W + kc * 32 * 64);
        #pragma unroll
        for (int i = tid; i < 512; i += 128) ((float4*)Ws)[i] = W4[i];
        #pragma unroll
        for (int i = tid; i < 1024; i += 128) {
            int row = i >> 3;
            int c4  = i & 7;
            int gr = row0 + row;
            float4 v = (gr < Nn) ? x4[(size_t)gr * 32 + kc * 8 + c4]
                                 : make_float4(0.f, 0.f, 0.f, 0.f);
            int col = (c4 * 4) ^ (((row >> 3) & 3) << 3);
            *(float4*)&Xs[row * 32 + col] = v;
        }
        __syncthreads();

        #pragma unroll
        for (int k = 0; k < 32; k++) {
            longlong2 w0 = *(const longlong2*)&Ws[k * 64 + ct * 8];
            longlong2 w1 = *(const longlong2*)&Ws[k * 64 + ct * 8 + 4];
            #pragma unroll
            for (int i = 0; i < 8; i++) {
                float xv = Xs[(r0 + i) * 32 + (k ^ kx)];
                unsigned long long xx;
                asm("mov.b64 %0, {%1, %1};" : "=l"(xx) : "r"(__float_as_uint(xv)));
                asm("fma.rn.f32x2 %0, %1, %2, %0;" : "+l"(acc[i][0]) : "l"(xx), "l"((unsigned long long)w0.x));
                asm("fma.rn.f32x2 %0, %1, %2, %0;" : "+l"(acc[i][1]) : "l"(xx), "l"((unsigned long long)w0.y));
                asm("fma.rn.f32x2 %0, %1, %2, %0;" : "+l"(acc[i][2]) : "l"(xx), "l"((unsigned long long)w1.x));
                asm("fma.rn.f32x2 %0, %1, %2, %0;" : "+l"(acc[i][3]) : "l"(xx), "l"((unsigned long long)w1.y));
            }
        }
        __syncthreads();
    }

    const float4* as4 = (const float4*)asv;
    const float4* ad4 = (const float4*)adv;
    float4 sa0 = as4[ct * 2], sa1 = as4[ct * 2 + 1];
    float4 da0 = ad4[ct * 2], da1 = ad4[ct * 2 + 1];

    #pragma unroll
    for (int i = 0; i < 8; i++) {
        int row = row0 + r0 + i;
        float o[8];
        #pragma unroll
        for (int j = 0; j < 4; j++) {
            unsigned int lo, hi;
            asm("mov.b64 {%0, %1}, %2;" : "=r"(lo), "=r"(hi) : "l"(acc[i][j]));
            o[2 * j]     = __uint_as_float(lo);
            o[2 * j + 1] = __uint_as_float(hi);
        }
        float ps = o[0]*sa0.x + o[1]*sa0.y + o[2]*sa0.z + o[3]*sa0.w
                 + o[4]*sa1.x + o[5]*sa1.y + o[6]*sa1.z + o[7]*sa1.w;
        float pd = o[0]*da0.x + o[1]*da0.y + o[2]*da0.z + o[3]*da0.w
                 + o[4]*da1.x + o[5]*da1.y + o[6]*da1.z + o[7]*da1.w;
        #pragma unroll
        for (int m = 1; m < 8; m <<= 1) {
            ps += __shfl_xor_sync(0xffffffffu, ps, m);
            pd += __shfl_xor_sync(0xffffffffu, pd, m);
        }
        if (row < Nn) {
            float* dstp = h + (size_t)row * 64 + ct * 8;
            *(float4*)dstp       = make_float4(o[0], o[1], o[2], o[3]);
            *(float4*)(dstp + 4) = make_float4(o[4], o[5], o[6], o[7]);
            if (ct == 0) { as_[row] = ps; ad_[row] = pd; }
        }
    }
}

// ---------------------------------------------------------------------------
// GEMM2: h2 = h1r @ W2 (K=64, C=40), alpha dots fused into epilogue.
// ---------------------------------------------------------------------------
__global__ void gemm2_kernel(const float* __restrict__ x,
                             const float* __restrict__ W,
                             const float* __restrict__ asv,
                             const float* __restrict__ adv,
                             float* __restrict__ h,
                             float* __restrict__ as_, float* __restrict__ ad_,
                             int Nn) {
    __shared__ float Xs[32][64];
    __shared__ float Ws[64][40];
    int tid = threadIdx.x;
    int row0 = blockIdx.x * 32;

    #pragma unroll
    for (int i = tid; i < 64 * 40; i += 128) Ws[i / 40][i % 40] = W[i];

    const float4* x4 = (const float4*)x;
    float4* Xs4 = (float4*)Xs;
    #pragma unroll
    for (int i = tid; i < 32 * 16; i += 128) {
        long long gi = (long long)row0 * 16 + i;
        Xs4[i] = (gi < (long long)Nn * 16) ? x4[gi] : make_float4(0.f, 0.f, 0.f, 0.f);
    }
    __syncthreads();

    int r0 = (tid >> 3) * 2;
    int c0 = (tid & 7) * 5;
    float acc[2][5] = {};
    #pragma unroll 4
    for (int k = 0; k < 64; k++) {
        float xv0 = Xs[r0][k];
        float xv1 = Xs[r0 + 1][k];
        #pragma unroll
        for (int j = 0; j < 5; j++) {
            float wv = Ws[k][c0 + j];
            acc[0][j] += xv0 * wv;
            acc[1][j] += xv1 * wv;
        }
    }

    float sa[5], da[5];
    #pragma unroll
    for (int j = 0; j < 5; j++) { sa[j] = asv[c0 + j]; da[j] = adv[c0 + j]; }

    #pragma unroll
    for (int i = 0; i < 2; i++) {
        int row = row0 + r0 + i;
        float ps = 0.f, pd = 0.f;
        #pragma unroll
        for (int j = 0; j < 5; j++) {
            ps += acc[i][j] * sa[j];
            pd += acc[i][j] * da[j];
        }
        #pragma unroll
        for (int m = 1; m < 8; m <<= 1) {
            ps += __shfl_xor_sync(0xffffffffu, ps, m);
            pd += __shfl_xor_sync(0xffffffffu, pd, m);
        }
        if (row < Nn) {
            float* dstp = h + (size_t)row * 40 + c0;
            #pragma unroll
            for (int j = 0; j < 5; j++) dstp[j] = acc[i][j];
            if ((tid & 7) == 0) { as_[row] = ps; ad_[row] = pd; }
        }
    }
}

// ---------------------------------------------------------------------------
// Fused GAT aggregation, one warp per destination (CSR), subwarp-parallel
// gather: 4 edges in flight per warp, 8 lanes per edge (1-2 float4 per lane).
// Pass 1 caches exp coefs in per-warp smem (deg<=96; fallback recompute).
// Epilogue: FINAL=false -> relu(acc+bias); FINAL=true -> fused log_softmax.
// ---------------------------------------------------------------------------
template <int F, bool FINAL>
__global__ void gat_agg_kernel(const int* __restrict__ srcs,
                               const int* __restrict__ off,
                               const float* __restrict__ as_,
                               const float* __restrict__ ad_,
                               const float* __restrict__ h,
                               const float* __restrict__ bias,
                               float* __restrict__ outp, int Nn) {
    constexpr int NV4 = F / 4;            // 16 (F=64) or 10 (F=40)
    __shared__ float exco[8][100];
    int w = threadIdx.x >> 5, lane = threadIdx.x & 31;
    int d = blockIdx.x * 8 + w;
    if (d >= Nn) return;
    int beg = off[d], end = off[d + 1];
    int deg = end - beg;
    float advv = ad_[d];
    float* exc = exco[w];
    bool fits = (deg <= 96);

    // Pass 1: lane-parallel exp + sum
    float sum = 0.f;
    for (int i = lane; i < deg; i += 32) {
        int s = srcs[beg + i];
        float e = as_[s] + advv;
        e = (e > 0.f) ? e : 0.2f * e;
        float xv = expf(e);
        if (fits) exc[i] = xv;
        sum += xv;
    }
    #pragma unroll
    for (int m = 16; m; m >>= 1) sum += __shfl_xor_sync(0xffffffffu, sum, m);
    float rden = 1.0f / sum;
    __syncwarp();

    // Pass 2: 4 edges per warp-iteration, 8 lanes per edge
    int g = lane >> 3, l8 = lane & 7;
    float4 a0 = make_float4(0.f, 0.f, 0.f, 0.f);
    float4 a1 = make_float4(0.f, 0.f, 0.f, 0.f);
    const float4* h4 = (const float4*)h;

    #pragma unroll 2
    for (int it = 0; it < deg; it += 4) {
        int e = it + g;
        if (e < deg) {
            int s = srcs[beg + e];
            float coef;
            if (fits) {
                coef = exc[e] * rden;
            } else {
                float ev = as_[s] + advv;
                ev = (ev > 0.f) ? ev : 0.2f * ev;
                coef = expf(ev) * rden;
            }
            const float4* row = h4 + (size_t)s * NV4;
            float4 v0 = __ldg(&row[l8]);
            a0.x = fmaf(v0.x, coef, a0.x);
            a0.y = fmaf(v0.y, coef, a0.y);
            a0.z = fmaf(v0.z, coef, a0.z);
            a0.w = fmaf(v0.w, coef, a0.w);
            if (F == 64 || l8 < NV4 - 8) {
                float4 v1 = __ldg(&row[8 + l8]);
                a1.x = fmaf(v1.x, coef, a1.x);
                a1.y = fmaf(v1.y, coef, a1.y);
                a1.z = fmaf(v1.z, coef, a1.z);
                a1.w = fmaf(v1.w, coef, a1.w);
            }
        }
    }

    // Combine the 4 subwarps (butterfly -> every lane holds its l8 column sums)
    #pragma unroll
    for (int m = 8; m < 32; m <<= 1) {
        a0.x += __shfl_xor_sync(0xffffffffu, a0.x, m);
        a0.y += __shfl_xor_sync(0xffffffffu, a0.y, m);
        a0.z += __shfl_xor_sync(0xffffffffu, a0.z, m);
        a0.w += __shfl_xor_sync(0xffffffffu, a0.w, m);
        a1.x += __shfl_xor_sync(0xffffffffu, a1.x, m);
        a1.y += __shfl_xor_sync(0xffffffffu, a1.y, m);
        a1.z += __shfl_xor_sync(0xffffffffu, a1.z, m);
        a1.w += __shfl_xor_sync(0xffffffffu, a1.w, m);
    }

    const float4* b4 = (const float4*)bias;
    if (!FINAL) {
        if (lane < 8) {
            float4 bb0 = b4[lane];
            float4 bb1 = b4[8 + lane];
            float4 o0 = make_float4(fmaxf(a0.x + bb0.x, 0.f), fmaxf(a0.y + bb0.y, 0.f),
                                    fmaxf(a0.z + bb0.z, 0.f), fmaxf(a0.w + bb0.w, 0.f));
            float4 o1 = make_float4(fmaxf(a1.x + bb1.x, 0.f), fmaxf(a1.y + bb1.y, 0.f),
                                    fmaxf(a1.z + bb1.z, 0.f), fmaxf(a1.w + bb1.w, 0.f));
            ((float4*)outp)[(size_t)d * NV4 + lane]     = o0;
            ((float4*)outp)[(size_t)d * NV4 + 8 + lane] = o1;
        }
    } else {
        // F=40: columns l8*4.. (a0) and (8+l8)*4.. for l8<2 (a1)
        float4 bb0 = b4[l8];
        float4 v0 = make_float4(a0.x + bb0.x, a0.y + bb0.y, a0.z + bb0.z, a0.w + bb0.w);
        bool has1 = (l8 < NV4 - 8);
        float4 v1 = make_float4(0.f, 0.f, 0.f, 0.f);
        if (has1) {
            float4 bb1 = b4[8 + l8];
            v1 = make_float4(a1.x + bb1.x, a1.y + bb1.y, a1.z + bb1.z, a1.w + bb1.w);
        }
        float mx = fmaxf(fmaxf(v0.x, v0.y), fmaxf(v0.z, v0.w));
        if (has1) mx = fmaxf(mx, fmaxf(fmaxf(v1.x, v1.y), fmaxf(v1.z, v1.w)));
        #pragma unroll
        for (int m = 1; m < 8; m <<= 1) mx = fmaxf(mx, __shfl_xor_sync(0xffffffffu, mx, m));
        float se = expf(v0.x - mx) + expf(v0.y - mx) + expf(v0.z - mx) + expf(v0.w - mx);
        if (has1) se += expf(v1.x - mx) + expf(v1.y - mx) + expf(v1.z - mx) + expf(v1.w - mx);
        #pragma unroll
        for (int m = 1; m < 8; m <<= 1) se += __shfl_xor_sync(0xffffffffu, se, m);
        float ls = mx + logf(se);
        if (lane < 8)
            ((float4*)outp)[(size_t)d * NV4 + lane] =
                make_float4(v0.x - ls, v0.y - ls, v0.z - ls, v0.w - ls);
        if (lane < NV4 - 8)
            ((float4*)outp)[(size_t)d * NV4 + 8 + lane] =
                make_float4(v1.x - ls, v1.y - ls, v1.z - ls, v1.w - ls);
    }
}

// ---------------------------------------------------------------------------
// Launch
// ---------------------------------------------------------------------------
extern "C" void kernel_launch(void* const* d_in, const int* in_sizes, int n_in,
                              void* d_out, int out_size) {
    const float* x       = (const float*)d_in[0];
    const unsigned int* ei_raw = (const unsigned int*)d_in[1];
    const float* W1      = (const float*)d_in[2];
    const float* a_src1  = (const float*)d_in[3];
    const float* a_dst1  = (const float*)d_in[4];
    const float* b1      = (const float*)d_in[5];
    const float* W2      = (const float*)d_in[6];
    const float* a_src2  = (const float*)d_in[7];
    const float* a_dst2  = (const float*)d_in[8];
    const float* b2      = (const float*)d_in[9];
    float* out           = (float*)d_out;

    int Nn = in_sizes[0] / 128;
    long long E = in_sizes[1] / 2;
    long long T = E + Nn;

    float *p_h1, *p_h1r, *p_h2, *p_as, *p_ad;
    int *p_idx, *p_cnt, *p_off, *p_cur, *p_srcs, *p_bsum, *p_is64;
    cudaGetSymbolAddress((void**)&p_h1, g_h1);
    cudaGetSymbolAddress((void**)&p_h1r, g_h1r);
    cudaGetSymbolAddress((void**)&p_h2, g_h2);
    cudaGetSymbolAddress((void**)&p_as, g_as);
    cudaGetSymbolAddress((void**)&p_ad, g_ad);
    cudaGetSymbolAddress((void**)&p_idx, g_idx);
    cudaGetSymbolAddress((void**)&p_cnt, g_cnt);
    cudaGetSymbolAddress((void**)&p_off, g_off);
    cudaGetSymbolAddress((void**)&p_cur, g_cur);
    cudaGetSymbolAddress((void**)&p_srcs, g_srcs);
    cudaGetSymbolAddress((void**)&p_bsum, g_bsum);
    cudaGetSymbolAddress((void**)&p_is64, g_is64);

    const int TB = 256;
    int nb = (Nn + 1023) / 1024;

    // ---- CSR build ----
    detect_idx_kernel<<<1, 256>>>(ei_raw, p_is64);
    init_cnt_kernel<<<(Nn + TB - 1) / TB, TB>>>(p_cnt, Nn);
    convert_hist_kernel<<<(int)((2 * E + TB - 1) / TB), TB>>>(ei_raw, p_idx, p_cnt, 2 * E, E, p_is64);
    scanA_kernel<<<nb, 1024>>>(p_cnt, p_off, p_bsum, Nn);
    scanB_kernel<<<1, 128>>>(p_bsum, nb);
    scanC_kernel<<<(Nn + TB - 1) / TB, TB>>>(p_off, p_cur, p_bsum, Nn, (int)T);
    fill_kernel<<<(int)((T + TB - 1) / TB), TB>>>(p_idx, p_cur, p_srcs, E, T);

    // ---- Layer 1 ----
    gemm1_kernel<<<(Nn + 127) / 128, 128>>>(x, W1, a_src1, a_dst1, p_h1, p_as, p_ad, Nn);
    gat_agg_kernel<64, false><<<(Nn + 7) / 8, 256>>>(p_srcs, p_off, p_as, p_ad, p_h1, b1, p_h1r, Nn);

    // ---- Layer 2 ----
    gemm2_kernel<<<(Nn + 31) / 32, 128>>>(p_h1r, W2, a_src2, a_dst2, p_h2, p_as, p_ad, Nn);
    gat_agg_kernel<40, true><<<(Nn + 7) / 8, 256>>>(p_srcs, p_off, p_as, p_ad, p_h2, b2, out, Nn);
}

// round 6
// speedup vs baseline: 1.8575x; 1.1056x over previous
#include <cuda_runtime.h>
#include <math.h>

// ---------------------------------------------------------------------------
// N=100000, F_in=128, F_hid=64, F_out=40, E=1600000 (+N self loops).
// ---------------------------------------------------------------------------
#define MAXN 100000
#define MAXE 1700096

__device__ float g_h1[(size_t)MAXN * 64];
__device__ float g_h1r[(size_t)MAXN * 64];
__device__ float g_h2[(size_t)MAXN * 40];
__device__ float g_as[MAXN];
__device__ float g_ad[MAXN];
__device__ int   g_idx[2 * 1600000];
__device__ int   g_cnt[MAXN];
__device__ int   g_off[MAXN + 1];
__device__ int   g_cur[MAXN];
__device__ int   g_srcs[MAXE];
__device__ int   g_bsum[128];
__device__ int   g_is64;

// ---------------------------------------------------------------------------
// Edge index dtype detection + conversion, dst histogram fused.
// ---------------------------------------------------------------------------
__global__ void detect_idx_kernel(const unsigned int* __restrict__ w, int* flag) {
    __shared__ int any;
    if (threadIdx.x == 0) any = 0;
    __syncthreads();
    for (int i = threadIdx.x; i < 1024; i += blockDim.x)
        if (w[2 * i + 1] != 0u) atomicOr(&any, 1);
    __syncthreads();
    if (threadIdx.x == 0) *flag = any ? 0 : 1;  // 1 => int64
}

__global__ void init_cnt_kernel(int* cnt, int n) {
    int i = blockIdx.x * blockDim.x + threadIdx.x;
    if (i < n) cnt[i] = 1;  // self loop
}

__global__ void convert_hist_kernel(const unsigned int* __restrict__ w,
                                    int* __restrict__ out, int* __restrict__ cnt,
                                    long long n2, long long E,
                                    const int* __restrict__ flag) {
    long long i = (long long)blockIdx.x * blockDim.x + threadIdx.x;
    if (i >= n2) return;
    int is64 = *flag;
    int v = (int)(is64 ? w[2 * i] : w[i]);
    out[i] = v;
    if (i >= E) atomicAdd(&cnt[v], 1);
}

// ---------------------------------------------------------------------------
// Two-level exclusive scan of cnt -> off
// ---------------------------------------------------------------------------
__global__ void scanA_kernel(const int* __restrict__ cnt, int* __restrict__ off,
                             int* __restrict__ bsum, int n) {
    __shared__ int sm[1024];
    int i = blockIdx.x * 1024 + threadIdx.x;
    int v = (i < n) ? cnt[i] : 0;
    sm[threadIdx.x] = v;
    __syncthreads();
    #pragma unroll
    for (int o = 1; o < 1024; o <<= 1) {
        int t = (threadIdx.x >= o) ? sm[threadIdx.x - o] : 0;
        __syncthreads();
        sm[threadIdx.x] += t;
        __syncthreads();
    }
    if (i < n) off[i] = sm[threadIdx.x] - v;
    if (threadIdx.x == 1023) bsum[blockIdx.x] = sm[1023];
}

__global__ void scanB_kernel(int* bsum, int nb) {
    __shared__ int sm[128];
    int v = (threadIdx.x < nb) ? bsum[threadIdx.x] : 0;
    sm[threadIdx.x] = v;
    __syncthreads();
    #pragma unroll
    for (int o = 1; o < 128; o <<= 1) {
        int t = (threadIdx.x >= o) ? sm[threadIdx.x - o] : 0;
        __syncthreads();
        sm[threadIdx.x] += t;
        __syncthreads();
    }
    if (threadIdx.x < nb) bsum[threadIdx.x] = sm[threadIdx.x] - v;
}

__global__ void scanC_kernel(int* __restrict__ off, int* __restrict__ cur,
                             const int* __restrict__ bsum, int n, int total) {
    int i = blockIdx.x * blockDim.x + threadIdx.x;
    if (i < n) {
        int o = off[i] + bsum[i >> 10];
        off[i] = o;
        cur[i] = o;
    }
    if (i == 0) off[n] = total;
}

__global__ void fill_kernel(const int* __restrict__ idx, int* __restrict__ cur,
                            int* __restrict__ srcs, long long E, long long T) {
    long long t = (long long)blockIdx.x * blockDim.x + threadIdx.x;
    if (t >= T) return;
    int s, d;
    if (t < E) { s = idx[t]; d = idx[t + E]; } else { s = d = (int)(t - E); }
    int pos = atomicAdd(&cur[d], 1);
    srcs[pos] = s;
}

// ---------------------------------------------------------------------------
// GEMM1: h = x @ W (K=128, C=64), 128x64/block, 128 threads, 8x8/thread,
// packed f32x2 FMAs, alpha dots fused into epilogue.
// ---------------------------------------------------------------------------
__global__ void gemm1_kernel(const float* __restrict__ x,
                             const float* __restrict__ W,
                             const float* __restrict__ asv,
                             const float* __restrict__ adv,
                             float* __restrict__ h,
                             float* __restrict__ as_, float* __restrict__ ad_,
                             int Nn) {
    __shared__ float Xs[128 * 32];
    __shared__ float Ws[32 * 64];
    int tid = threadIdx.x;
    int row0 = blockIdx.x * 128;
    int rt = tid >> 3;
    int ct = tid & 7;
    int r0 = rt * 8;
    int kx = (rt & 3) << 3;

    unsigned long long acc[8][4];
    #pragma unroll
    for (int i = 0; i < 8; i++)
        #pragma unroll
        for (int j = 0; j < 4; j++) acc[i][j] = 0ull;

    const float4* x4 = (const float4*)x;

    for (int kc = 0; kc < 4; kc++) {
        const float4* W4 = (const float4*)(W + kc * 32 * 64);
        #pragma unroll
        for (int i = tid; i < 512; i += 128) ((float4*)Ws)[i] = W4[i];
        #pragma unroll
        for (int i = tid; i < 1024; i += 128) {
            int row = i >> 3;
            int c4  = i & 7;
            int gr = row0 + row;
            float4 v = (gr < Nn) ? x4[(size_t)gr * 32 + kc * 8 + c4]
                                 : make_float4(0.f, 0.f, 0.f, 0.f);
            int col = (c4 * 4) ^ (((row >> 3) & 3) << 3);
            *(float4*)&Xs[row * 32 + col] = v;
        }
        __syncthreads();

        #pragma unroll
        for (int k = 0; k < 32; k++) {
            longlong2 w0 = *(const longlong2*)&Ws[k * 64 + ct * 8];
            longlong2 w1 = *(const longlong2*)&Ws[k * 64 + ct * 8 + 4];
            #pragma unroll
            for (int i = 0; i < 8; i++) {
                float xv = Xs[(r0 + i) * 32 + (k ^ kx)];
                unsigned long long xx;
                asm("mov.b64 %0, {%1, %1};" : "=l"(xx) : "r"(__float_as_uint(xv)));
                asm("fma.rn.f32x2 %0, %1, %2, %0;" : "+l"(acc[i][0]) : "l"(xx), "l"((unsigned long long)w0.x));
                asm("fma.rn.f32x2 %0, %1, %2, %0;" : "+l"(acc[i][1]) : "l"(xx), "l"((unsigned long long)w0.y));
                asm("fma.rn.f32x2 %0, %1, %2, %0;" : "+l"(acc[i][2]) : "l"(xx), "l"((unsigned long long)w1.x));
                asm("fma.rn.f32x2 %0, %1, %2, %0;" : "+l"(acc[i][3]) : "l"(xx), "l"((unsigned long long)w1.y));
            }
        }
        __syncthreads();
    }

    const float4* as4 = (const float4*)asv;
    const float4* ad4 = (const float4*)adv;
    float4 sa0 = as4[ct * 2], sa1 = as4[ct * 2 + 1];
    float4 da0 = ad4[ct * 2], da1 = ad4[ct * 2 + 1];

    #pragma unroll
    for (int i = 0; i < 8; i++) {
        int row = row0 + r0 + i;
        float o[8];
        #pragma unroll
        for (int j = 0; j < 4; j++) {
            unsigned int lo, hi;
            asm("mov.b64 {%0, %1}, %2;" : "=r"(lo), "=r"(hi) : "l"(acc[i][j]));
            o[2 * j]     = __uint_as_float(lo);
            o[2 * j + 1] = __uint_as_float(hi);
        }
        float ps = o[0]*sa0.x + o[1]*sa0.y + o[2]*sa0.z + o[3]*sa0.w
                 + o[4]*sa1.x + o[5]*sa1.y + o[6]*sa1.z + o[7]*sa1.w;
        float pd = o[0]*da0.x + o[1]*da0.y + o[2]*da0.z + o[3]*da0.w
                 + o[4]*da1.x + o[5]*da1.y + o[6]*da1.z + o[7]*da1.w;
        #pragma unroll
        for (int m = 1; m < 8; m <<= 1) {
            ps += __shfl_xor_sync(0xffffffffu, ps, m);
            pd += __shfl_xor_sync(0xffffffffu, pd, m);
        }
        if (row < Nn) {
            float* dstp = h + (size_t)row * 64 + ct * 8;
            *(float4*)dstp       = make_float4(o[0], o[1], o[2], o[3]);
            *(float4*)(dstp + 4) = make_float4(o[4], o[5], o[6], o[7]);
            if (ct == 0) { as_[row] = ps; ad_[row] = pd; }
        }
    }
}

// ---------------------------------------------------------------------------
// GEMM2: h2 = h1r @ W2 (K=64, C=40), alpha dots fused into epilogue.
// ---------------------------------------------------------------------------
__global__ void gemm2_kernel(const float* __restrict__ x,
                             const float* __restrict__ W,
                             const float* __restrict__ asv,
                             const float* __restrict__ adv,
                             float* __restrict__ h,
                             float* __restrict__ as_, float* __restrict__ ad_,
                             int Nn) {
    __shared__ float Xs[32][64];
    __shared__ float Ws[64][40];
    int tid = threadIdx.x;
    int row0 = blockIdx.x * 32;

    #pragma unroll
    for (int i = tid; i < 64 * 40; i += 128) Ws[i / 40][i % 40] = W[i];

    const float4* x4 = (const float4*)x;
    float4* Xs4 = (float4*)Xs;
    #pragma unroll
    for (int i = tid; i < 32 * 16; i += 128) {
        long long gi = (long long)row0 * 16 + i;
        Xs4[i] = (gi < (long long)Nn * 16) ? x4[gi] : make_float4(0.f, 0.f, 0.f, 0.f);
    }
    __syncthreads();

    int r0 = (tid >> 3) * 2;
    int c0 = (tid & 7) * 5;
    float acc[2][5] = {};
    #pragma unroll 4
    for (int k = 0; k < 64; k++) {
        float xv0 = Xs[r0][k];
        float xv1 = Xs[r0 + 1][k];
        #pragma unroll
        for (int j = 0; j < 5; j++) {
            float wv = Ws[k][c0 + j];
            acc[0][j] += xv0 * wv;
            acc[1][j] += xv1 * wv;
        }
    }

    float sa[5], da[5];
    #pragma unroll
    for (int j = 0; j < 5; j++) { sa[j] = asv[c0 + j]; da[j] = adv[c0 + j]; }

    #pragma unroll
    for (int i = 0; i < 2; i++) {
        int row = row0 + r0 + i;
        float ps = 0.f, pd = 0.f;
        #pragma unroll
        for (int j = 0; j < 5; j++) {
            ps += acc[i][j] * sa[j];
            pd += acc[i][j] * da[j];
        }
        #pragma unroll
        for (int m = 1; m < 8; m <<= 1) {
            ps += __shfl_xor_sync(0xffffffffu, ps, m);
            pd += __shfl_xor_sync(0xffffffffu, pd, m);
        }
        if (row < Nn) {
            float* dstp = h + (size_t)row * 40 + c0;
            #pragma unroll
            for (int j = 0; j < 5; j++) dstp[j] = acc[i][j];
            if ((tid & 7) == 0) { as_[row] = ps; ad_[row] = pd; }
        }
    }
}

// ---------------------------------------------------------------------------
// Fused GAT aggregation, one warp per destination (CSR).
// Pass 1 caches exp coefs in smem (deg<=96; recompute fallback).
// Pass 2: branchless batched gather, 8 edges per warp-iteration
// (2 per 8-lane subwarp), out-of-range edges get coef=0 with clamped index,
// so all LDG.128 issue unconditionally and front-batch (high MLP).
// Epilogue: FINAL=false -> relu(acc+bias); FINAL=true -> fused log_softmax.
// ---------------------------------------------------------------------------
template <int F, bool FINAL>
__global__ void gat_agg_kernel(const int* __restrict__ srcs,
                               const int* __restrict__ off,
                               const float* __restrict__ as_,
                               const float* __restrict__ ad_,
                               const float* __restrict__ h,
                               const float* __restrict__ bias,
                               float* __restrict__ outp, int Nn) {
    constexpr int NV4 = F / 4;
    __shared__ float exco[8][100];
    int w = threadIdx.x >> 5, lane = threadIdx.x & 31;
    int d = blockIdx.x * 8 + w;
    if (d >= Nn) return;
    int beg = off[d], end = off[d + 1];
    int deg = end - beg;
    float advv = ad_[d];
    float* exc = exco[w];
    bool fits = (deg <= 96);

    // Pass 1: lane-parallel exp + sum
    float sum = 0.f;
    for (int i = lane; i < deg; i += 32) {
        int s = srcs[beg + i];
        float e = as_[s] + advv;
        e = (e > 0.f) ? e : 0.2f * e;
        float xv = expf(e);
        if (fits) exc[i] = xv;
        sum += xv;
    }
    #pragma unroll
    for (int m = 16; m; m >>= 1) sum += __shfl_xor_sync(0xffffffffu, sum, m);
    float rden = 1.0f / sum;
    __syncwarp();

    int g = lane >> 3, l8 = lane & 7;
    float4 a0 = make_float4(0.f, 0.f, 0.f, 0.f);
    float4 a1 = make_float4(0.f, 0.f, 0.f, 0.f);
    const float4* h4 = (const float4*)h;
    const bool has1 = (F == 64) || (l8 < NV4 - 8);

    if (fits) {
        for (int it = 0; it < deg; it += 8) {
            int e0 = it + g;
            int e1 = it + 4 + g;
            int i0 = min(e0, deg - 1);
            int i1 = min(e1, deg - 1);
            int s0 = srcs[beg + i0];
            int s1 = srcs[beg + i1];
            float c0 = exc[i0] * rden; if (e0 >= deg) c0 = 0.f;
            float c1 = exc[i1] * rden; if (e1 >= deg) c1 = 0.f;
            const float4* r0p = h4 + (size_t)s0 * NV4;
            const float4* r1p = h4 + (size_t)s1 * NV4;
            float4 v00 = __ldg(&r0p[l8]);
            float4 v10 = __ldg(&r1p[l8]);
            float4 v01, v11;
            if (has1) { v01 = __ldg(&r0p[8 + l8]); v11 = __ldg(&r1p[8 + l8]); }
            a0.x = fmaf(v00.x, c0, a0.x); a0.y = fmaf(v00.y, c0, a0.y);
            a0.z = fmaf(v00.z, c0, a0.z); a0.w = fmaf(v00.w, c0, a0.w);
            a0.x = fmaf(v10.x, c1, a0.x); a0.y = fmaf(v10.y, c1, a0.y);
            a0.z = fmaf(v10.z, c1, a0.z); a0.w = fmaf(v10.w, c1, a0.w);
            if (has1) {
                a1.x = fmaf(v01.x, c0, a1.x); a1.y = fmaf(v01.y, c0, a1.y);
                a1.z = fmaf(v01.z, c0, a1.z); a1.w = fmaf(v01.w, c0, a1.w);
                a1.x = fmaf(v11.x, c1, a1.x); a1.y = fmaf(v11.y, c1, a1.y);
                a1.z = fmaf(v11.z, c1, a1.z); a1.w = fmaf(v11.w, c1, a1.w);
            }
        }
    } else {
        for (int it = 0; it < deg; it += 4) {
            int e = it + g;
            if (e < deg) {
                int s = srcs[beg + e];
                float ev = as_[s] + advv;
                ev = (ev > 0.f) ? ev : 0.2f * ev;
                float coef = expf(ev) * rden;
                const float4* row = h4 + (size_t)s * NV4;
                float4 v0 = __ldg(&row[l8]);
                a0.x = fmaf(v0.x, coef, a0.x); a0.y = fmaf(v0.y, coef, a0.y);
                a0.z = fmaf(v0.z, coef, a0.z); a0.w = fmaf(v0.w, coef, a0.w);
                if (has1) {
                    float4 v1 = __ldg(&row[8 + l8]);
                    a1.x = fmaf(v1.x, coef, a1.x); a1.y = fmaf(v1.y, coef, a1.y);
                    a1.z = fmaf(v1.z, coef, a1.z); a1.w = fmaf(v1.w, coef, a1.w);
                }
            }
        }
    }

    // Combine the 4 subwarps
    #pragma unroll
    for (int m = 8; m < 32; m <<= 1) {
        a0.x += __shfl_xor_sync(0xffffffffu, a0.x, m);
        a0.y += __shfl_xor_sync(0xffffffffu, a0.y, m);
        a0.z += __shfl_xor_sync(0xffffffffu, a0.z, m);
        a0.w += __shfl_xor_sync(0xffffffffu, a0.w, m);
        a1.x += __shfl_xor_sync(0xffffffffu, a1.x, m);
        a1.y += __shfl_xor_sync(0xffffffffu, a1.y, m);
        a1.z += __shfl_xor_sync(0xffffffffu, a1.z, m);
        a1.w += __shfl_xor_sync(0xffffffffu, a1.w, m);
    }

    const float4* b4 = (const float4*)bias;
    if (!FINAL) {
        if (lane < 8) {
            float4 bb0 = b4[lane];
            float4 bb1 = b4[8 + lane];
            float4 o0 = make_float4(fmaxf(a0.x + bb0.x, 0.f), fmaxf(a0.y + bb0.y, 0.f),
                                    fmaxf(a0.z + bb0.z, 0.f), fmaxf(a0.w + bb0.w, 0.f));
            float4 o1 = make_float4(fmaxf(a1.x + bb1.x, 0.f), fmaxf(a1.y + bb1.y, 0.f),
                                    fmaxf(a1.z + bb1.z, 0.f), fmaxf(a1.w + bb1.w, 0.f));
            ((float4*)outp)[(size_t)d * NV4 + lane]     = o0;
            ((float4*)outp)[(size_t)d * NV4 + 8 + lane] = o1;
        }
    } else {
        float4 bb0 = b4[l8];
        float4 v0 = make_float4(a0.x + bb0.x, a0.y + bb0.y, a0.z + bb0.z, a0.w + bb0.w);
        float4 v1 = make_float4(0.f, 0.f, 0.f, 0.f);
        if (has1) {
            float4 bb1 = b4[8 + l8];
            v1 = make_float4(a1.x + bb1.x, a1.y + bb1.y, a1.z + bb1.z, a1.w + bb1.w);
        }
        float mx = fmaxf(fmaxf(v0.x, v0.y), fmaxf(v0.z, v0.w));
        if (has1) mx = fmaxf(mx, fmaxf(fmaxf(v1.x, v1.y), fmaxf(v1.z, v1.w)));
        #pragma unroll
        for (int m = 1; m < 8; m <<= 1) mx = fmaxf(mx, __shfl_xor_sync(0xffffffffu, mx, m));
        float se = expf(v0.x - mx) + expf(v0.y - mx) + expf(v0.z - mx) + expf(v0.w - mx);
        if (has1) se += expf(v1.x - mx) + expf(v1.y - mx) + expf(v1.z - mx) + expf(v1.w - mx);
        #pragma unroll
        for (int m = 1; m < 8; m <<= 1) se += __shfl_xor_sync(0xffffffffu, se, m);
        float ls = mx + logf(se);
        if (lane < 8)
            ((float4*)outp)[(size_t)d * NV4 + lane] =
                make_float4(v0.x - ls, v0.y - ls, v0.z - ls, v0.w - ls);
        if (lane < NV4 - 8)
            ((float4*)outp)[(size_t)d * NV4 + 8 + lane] =
                make_float4(v1.x - ls, v1.y - ls, v1.z - ls, v1.w - ls);
    }
}

// ---------------------------------------------------------------------------
// Launch: CSR build runs on a side stream, overlapped with gemm1.
// ---------------------------------------------------------------------------
extern "C" void kernel_launch(void* const* d_in, const int* in_sizes, int n_in,
                              void* d_out, int out_size) {
    const float* x       = (const float*)d_in[0];
    const unsigned int* ei_raw = (const unsigned int*)d_in[1];
    const float* W1      = (const float*)d_in[2];
    const float* a_src1  = (const float*)d_in[3];
    const float* a_dst1  = (const float*)d_in[4];
    const float* b1      = (const float*)d_in[5];
    const float* W2      = (const float*)d_in[6];
    const float* a_src2  = (const float*)d_in[7];
    const float* a_dst2  = (const float*)d_in[8];
    const float* b2      = (const float*)d_in[9];
    float* out           = (float*)d_out;

    int Nn = in_sizes[0] / 128;
    long long E = in_sizes[1] / 2;
    long long T = E + Nn;

    float *p_h1, *p_h1r, *p_h2, *p_as, *p_ad;
    int *p_idx, *p_cnt, *p_off, *p_cur, *p_srcs, *p_bsum, *p_is64;
    cudaGetSymbolAddress((void**)&p_h1, g_h1);
    cudaGetSymbolAddress((void**)&p_h1r, g_h1r);
    cudaGetSymbolAddress((void**)&p_h2, g_h2);
    cudaGetSymbolAddress((void**)&p_as, g_as);
    cudaGetSymbolAddress((void**)&p_ad, g_ad);
    cudaGetSymbolAddress((void**)&p_idx, g_idx);
    cudaGetSymbolAddress((void**)&p_cnt, g_cnt);
    cudaGetSymbolAddress((void**)&p_off, g_off);
    cudaGetSymbolAddress((void**)&p_cur, g_cur);
    cudaGetSymbolAddress((void**)&p_srcs, g_srcs);
    cudaGetSymbolAddress((void**)&p_bsum, g_bsum);
    cudaGetSymbolAddress((void**)&p_is64, g_is64);

    // One-time host-side resources (no device work, no device memory).
    static cudaStream_t s2 = nullptr;
    static cudaEvent_t evF = nullptr, evC = nullptr;
    if (!s2) {
        cudaStreamCreateWithFlags(&s2, cudaStreamNonBlocking);
        cudaEventCreateWithFlags(&evF, cudaEventDisableTiming);
        cudaEventCreateWithFlags(&evC, cudaEventDisableTiming);
    }

    const int TB = 256;
    int nb = (Nn + 1023) / 1024;

    // ---- Fork: CSR build on s2, gemm1 on main stream ----
    cudaEventRecord(evF, 0);
    cudaStreamWaitEvent(s2, evF, 0);

    detect_idx_kernel<<<1, 256, 0, s2>>>(ei_raw, p_is64);
    init_cnt_kernel<<<(Nn + TB - 1) / TB, TB, 0, s2>>>(p_cnt, Nn);
    convert_hist_kernel<<<(int)((2 * E + TB - 1) / TB), TB, 0, s2>>>(ei_raw, p_idx, p_cnt, 2 * E, E, p_is64);
    scanA_kernel<<<nb, 1024, 0, s2>>>(p_cnt, p_off, p_bsum, Nn);
    scanB_kernel<<<1, 128, 0, s2>>>(p_bsum, nb);
    scanC_kernel<<<(Nn + TB - 1) / TB, TB, 0, s2>>>(p_off, p_cur, p_bsum, Nn, (int)T);
    fill_kernel<<<(int)((T + TB - 1) / TB), TB, 0, s2>>>(p_idx, p_cur, p_srcs, E, T);
    cudaEventRecord(evC, s2);

    gemm1_kernel<<<(Nn + 127) / 128, 128>>>(x, W1, a_src1, a_dst1, p_h1, p_as, p_ad, Nn);

    // ---- Join, then rest of the pipeline on the main stream ----
    cudaStreamWaitEvent(0, evC, 0);
    gat_agg_kernel<64, false><<<(Nn + 7) / 8, 256>>>(p_srcs, p_off, p_as, p_ad, p_h1, b1, p_h1r, Nn);
    gemm2_kernel<<<(Nn + 31) / 32, 128>>>(p_h1r, W2, a_src2, a_dst2, p_h2, p_as, p_ad, Nn);
    gat_agg_kernel<40, true><<<(Nn + 7) / 8, 256>>>(p_srcs, p_off, p_as, p_ad, p_h2, b2, out, Nn);
}